// round 6
// baseline (speedup 1.0000x reference)
#include <cuda_runtime.h>
#include <cuda_bf16.h>
#include <mma.h>
#include <cstdint>
#include <math.h>

using namespace nvcuda;

#define HH 12
#define NP 196
#define FF 8
#define DIMM 768
#define D3 192
#define BB 8
#define SS 1569
#define PP 195
#define C3 2304
#define SCALE_INV (1.0f/96.0f)

#define M1PAD 12672   // ceil(8*1569/128)*128
#define M2PAD 1664    // ceil(8*195/128)*128

// ---------------- scratch (device globals) ----------------------------------
__device__ float g_xq[BB*SS*C3];
__device__ float g_xk[BB*SS*C3];
__device__ float g_xv[BB*SS*C3];
__device__ float g_t1[BB*PP*C3];
__device__ float g_ti[BB*PP*DIMM];
__device__ float g_q2[BB*PP*C3];
__device__ float g_k2[BB*PP*C3];
__device__ float g_v2[BB*PP*C3];
__device__ float g_cls[BB*C3];
__device__ float g_t2[BB*FF*C3];
__device__ float g_rows[BB*9*DIMM];
__device__ __nv_bfloat16 g_xhi[M1PAD*DIMM],  g_xlo[M1PAD*DIMM];
__device__ __nv_bfloat16 g_t1hi[M2PAD*C3],   g_t1lo[M2PAD*C3];
__device__ __nv_bfloat16 g_tihi[M2PAD*DIMM], g_tilo[M2PAD*DIMM];
__device__ __nv_bfloat16 g_WqThi[C3*DIMM], g_WqTlo[C3*DIMM];
__device__ __nv_bfloat16 g_WkThi[C3*DIMM], g_WkTlo[C3*DIMM];
__device__ __nv_bfloat16 g_WvThi[C3*DIMM], g_WvTlo[C3*DIMM];
__device__ __nv_bfloat16 g_WtThi[DIMM*C3], g_WtTlo[DIMM*C3];

// ---------------- cp.async helpers ------------------------------------------
__device__ __forceinline__ uint32_t smem_u32(const void* p) {
    uint32_t a;
    asm("{ .reg .u64 t; cvta.to.shared.u64 t, %1; cvt.u32.u64 %0, t; }" : "=r"(a) : "l"(p));
    return a;
}
#define CP_ASYNC16(dst_u32, src_ptr) \
    asm volatile("cp.async.cg.shared.global [%0], [%1], 16;" :: "r"(dst_u32), "l"(src_ptr))
#define CP_COMMIT() asm volatile("cp.async.commit_group;" ::: "memory")
#define CP_WAIT1()  asm volatile("cp.async.wait_group 1;" ::: "memory")

// ---------------- split: fp32 -> bf16 hi + bf16 lo --------------------------
__global__ void split_f32(const float* __restrict__ in, __nv_bfloat16* __restrict__ hi,
                          __nv_bfloat16* __restrict__ lo, int n4) {
    int i = blockIdx.x * blockDim.x + threadIdx.x;
    if (i >= n4) return;
    float4 v = ((const float4*)in)[i];
    __nv_bfloat16 h0 = __float2bfloat16(v.x), h1 = __float2bfloat16(v.y);
    __nv_bfloat16 h2 = __float2bfloat16(v.z), h3 = __float2bfloat16(v.w);
    __nv_bfloat162 lo01(__float2bfloat16(v.x - __bfloat162float(h0)),
                        __float2bfloat16(v.y - __bfloat162float(h1)));
    __nv_bfloat162 lo23(__float2bfloat16(v.z - __bfloat162float(h2)),
                        __float2bfloat16(v.w - __bfloat162float(h3)));
    ((__nv_bfloat162*)hi)[i * 2 + 0] = __nv_bfloat162(h0, h1);
    ((__nv_bfloat162*)hi)[i * 2 + 1] = __nv_bfloat162(h2, h3);
    ((__nv_bfloat162*)lo)[i * 2 + 0] = lo01;
    ((__nv_bfloat162*)lo)[i * 2 + 1] = lo23;
}

// ---------------- transpose + split: fp32 [K,N] -> bf16 hi/lo [N,K] ---------
__global__ void transpose_split(const float* __restrict__ in,
                                __nv_bfloat16* __restrict__ hi,
                                __nv_bfloat16* __restrict__ lo, int K, int N) {
    __shared__ float t[32][33];
    const int n0 = blockIdx.x * 32, k0 = blockIdx.y * 32;
    const int tx = threadIdx.x & 31, ty = threadIdx.x >> 5;
#pragma unroll
    for (int i = 0; i < 32; i += 8)
        t[ty + i][tx] = in[(size_t)(k0 + ty + i) * N + n0 + tx];
    __syncthreads();
#pragma unroll
    for (int i = 0; i < 32; i += 8) {
        float v = t[tx][ty + i];
        __nv_bfloat16 h = __float2bfloat16(v);
        hi[(size_t)(n0 + ty + i) * K + k0 + tx] = h;
        lo[(size_t)(n0 + ty + i) * K + k0 + tx] = __float2bfloat16(v - __bfloat162float(h));
    }
}

#define LDT 40

// ================= BIG GEMM: BM=128, BN=256, warp tile 64x64, 1 CTA/SM ======
// C(MxN) = [Ahi+Alo] @ [Bhi+Blo]^T + bias (3-pass). N%256==0, K%32==0.
#define BT_A (128 * LDT * 2)          // 10240 B per A tile
#define BT_B (256 * LDT * 2)          // 20480 B per B tile
#define BSTAGE (2 * BT_A + 2 * BT_B)  // 61440 B per stage

__global__ void __launch_bounds__(256, 1)
gemm_big(const __nv_bfloat16* __restrict__ Ahi, const __nv_bfloat16* __restrict__ Alo,
         const __nv_bfloat16* __restrict__ Bhi, const __nv_bfloat16* __restrict__ Blo,
         const float* __restrict__ bias, float* __restrict__ C,
         int M, int N, int K) {
    extern __shared__ char smem[];
    const uint32_t smem_b = smem_u32(smem);
    const int tid = threadIdx.x;
    const int wid = tid >> 5, lane = tid & 31;
    const int wm = wid >> 2, wn = wid & 3;       // 2 x 4 warp grid
    const int rowA0 = blockIdx.y * 128;
    const int n0 = blockIdx.x * 256;
    const int nch = K >> 5;

    // ---- bias -> acc init (16-row replicated bias tile in smem) ----
    wmma::fragment<wmma::accumulator, 16, 16, 16, float> acc[4][4];
    {
        float* bt = (float*)smem;   // 16 x 256 floats
        const int c = tid;          // 256 threads -> 256 cols
        const float bv = bias[n0 + c];
#pragma unroll
        for (int r = 0; r < 16; r++) bt[r * 256 + c] = bv;
        __syncthreads();
#pragma unroll
        for (int j = 0; j < 4; j++) {
            wmma::load_matrix_sync(acc[0][j], bt + wn * 64 + j * 16, 256, wmma::mem_row_major);
#pragma unroll
            for (int i = 1; i < 4; i++) acc[i][j] = acc[0][j];
        }
        __syncthreads();
    }

    // ---- cp.async coordinates ----
    const int rA = tid >> 1, sA = (tid & 1) * 2;      // A: 2 segs of row rA
    const __nv_bfloat16* srcAh = Ahi + (size_t)(rowA0 + rA) * K + sA * 8;
    const __nv_bfloat16* srcAl = Alo + (size_t)(rowA0 + rA) * K + sA * 8;
    const __nv_bfloat16* srcBh = Bhi + (size_t)(n0 + tid) * K;   // B: full row tid
    const __nv_bfloat16* srcBl = Blo + (size_t)(n0 + tid) * K;
    const uint32_t dA = smem_b + rA * (LDT * 2) + sA * 16;
    const uint32_t dB = smem_b + tid * (LDT * 2);

    auto issue_stage = [&](int c, int buf) {
        const int k0 = c << 5;
        const uint32_t sb = buf * BSTAGE;
        CP_ASYNC16(dA + sb, srcAh + k0);
        CP_ASYNC16(dA + sb + 16, srcAh + k0 + 8);
        CP_ASYNC16(dA + sb + BT_A, srcAl + k0);
        CP_ASYNC16(dA + sb + BT_A + 16, srcAl + k0 + 8);
        const uint32_t bB = dB + sb + 2 * BT_A;
#pragma unroll
        for (int s = 0; s < 4; s++) {
            CP_ASYNC16(bB + s * 16, srcBh + k0 + s * 8);
            CP_ASYNC16(bB + BT_B + s * 16, srcBl + k0 + s * 8);
        }
    };

    issue_stage(0, 0);
    CP_COMMIT();

    for (int c = 0; c < nch; c++) {
        if (c + 1 < nch) issue_stage(c + 1, (c + 1) & 1);
        CP_COMMIT();
        CP_WAIT1();
        __syncthreads();

        const __nv_bfloat16* Ah = (const __nv_bfloat16*)(smem + (c & 1) * BSTAGE);
        const __nv_bfloat16* Al = Ah + 128 * LDT;
        const __nv_bfloat16* Bh = Al + 128 * LDT;
        const __nv_bfloat16* Bl = Bh + 256 * LDT;
#pragma unroll
        for (int kk = 0; kk < 32; kk += 16) {
            wmma::fragment<wmma::matrix_a, 16, 16, 16, __nv_bfloat16, wmma::row_major> ah[4], al[4];
#pragma unroll
            for (int i = 0; i < 4; i++) {
                wmma::load_matrix_sync(ah[i], Ah + (wm * 64 + i * 16) * LDT + kk, LDT);
                wmma::load_matrix_sync(al[i], Al + (wm * 64 + i * 16) * LDT + kk, LDT);
            }
#pragma unroll
            for (int j = 0; j < 4; j++) {
                wmma::fragment<wmma::matrix_b, 16, 16, 16, __nv_bfloat16, wmma::col_major> bh, bl;
                wmma::load_matrix_sync(bh, Bh + (wn * 64 + j * 16) * LDT + kk, LDT);
                wmma::load_matrix_sync(bl, Bl + (wn * 64 + j * 16) * LDT + kk, LDT);
#pragma unroll
                for (int i = 0; i < 4; i++) {
                    wmma::mma_sync(acc[i][j], ah[i], bh, acc[i][j]);
                    wmma::mma_sync(acc[i][j], ah[i], bl, acc[i][j]);
                    wmma::mma_sync(acc[i][j], al[i], bh, acc[i][j]);
                }
            }
        }
        __syncthreads();
    }

    // ---- epilogue: direct store (bias already in acc) ----
    if (rowA0 + 128 <= M) {
#pragma unroll
        for (int i = 0; i < 4; i++)
#pragma unroll
            for (int j = 0; j < 4; j++)
                wmma::store_matrix_sync(C + (size_t)(rowA0 + wm * 64 + i * 16) * N
                                          + n0 + wn * 64 + j * 16,
                                        acc[i][j], N, wmma::mem_row_major);
    } else {
        float* buf = (float*)(smem + wid * 1024);   // 16x16 per-warp patch
#pragma unroll
        for (int i = 0; i < 4; i++)
#pragma unroll
            for (int j = 0; j < 4; j++) {
                const int m0 = rowA0 + wm * 64 + i * 16;
                wmma::store_matrix_sync(buf, acc[i][j], 16, wmma::mem_row_major);
                __syncwarp();
#pragma unroll
                for (int e = 0; e < 8; e++) {
                    const int f = e * 32 + lane;
                    const int r = f >> 4, cc = f & 15;
                    if (m0 + r < M)
                        C[(size_t)(m0 + r) * N + n0 + wn * 64 + j * 16 + cc] = buf[r * 16 + cc];
                }
                __syncwarp();
            }
    }
}

// ================= small GEMM: 128x128, 2 CTA/SM (for ti) ===================
#define TILE_B (128 * LDT * 2)
#define STAGE_B (4 * TILE_B)
#define NSTAGE 2

__global__ void __launch_bounds__(256, 2)
gemm_bs(const __nv_bfloat16* __restrict__ Ahi, const __nv_bfloat16* __restrict__ Alo,
        const __nv_bfloat16* __restrict__ Bhi, const __nv_bfloat16* __restrict__ Blo,
        const float* __restrict__ bias, float* __restrict__ C,
        int M, int N, int K) {
    extern __shared__ char smem[];
    const uint32_t smem_b = smem_u32(smem);
    const int tid = threadIdx.x;
    const int wid = tid >> 5;
    const int wm = wid & 3, wn = wid >> 2;
    const int rowA0 = blockIdx.y * 128;
    const int n0 = blockIdx.x * 128;
    const int nch = K >> 5;

    const int r_cp = tid >> 1;
    const int s_cp = (tid & 1) * 2;
    const __nv_bfloat16* srcs[4];
    srcs[0] = Ahi + (size_t)(rowA0 + r_cp) * K;
    srcs[1] = Alo + (size_t)(rowA0 + r_cp) * K;
    srcs[2] = Bhi + (size_t)(n0 + r_cp) * K;
    srcs[3] = Blo + (size_t)(n0 + r_cp) * K;
    const uint32_t dst_row = smem_b + r_cp * (LDT * 2);

    auto issue_stage = [&](int c, int buf) {
        const int k0 = c << 5;
        const uint32_t sb = buf * STAGE_B;
#pragma unroll
        for (int t = 0; t < 4; t++) {
            const __nv_bfloat16* src = srcs[t] + k0 + s_cp * 8;
            const uint32_t dst = dst_row + sb + t * TILE_B + s_cp * 16;
            CP_ASYNC16(dst, src);
            CP_ASYNC16(dst + 16, src + 8);
        }
    };

    wmma::fragment<wmma::accumulator, 16, 16, 16, float> acc[2][4];
#pragma unroll
    for (int i = 0; i < 2; i++)
#pragma unroll
        for (int j = 0; j < 4; j++) wmma::fill_fragment(acc[i][j], 0.f);

    issue_stage(0, 0);
    CP_COMMIT();

    for (int c = 0; c < nch; c++) {
        if (c + 1 < nch) issue_stage(c + 1, (c + 1) & 1);
        CP_COMMIT();
        CP_WAIT1();
        __syncthreads();

        const __nv_bfloat16* Ah = (const __nv_bfloat16*)(smem + (c & 1) * STAGE_B);
        const __nv_bfloat16* Al = Ah + 128 * LDT;
        const __nv_bfloat16* Bh = Al + 128 * LDT;
        const __nv_bfloat16* Bl = Bh + 128 * LDT;
#pragma unroll
        for (int kk = 0; kk < 32; kk += 16) {
            wmma::fragment<wmma::matrix_a, 16, 16, 16, __nv_bfloat16, wmma::row_major> ah[2], al[2];
#pragma unroll
            for (int i = 0; i < 2; i++) {
                wmma::load_matrix_sync(ah[i], Ah + (wm * 32 + i * 16) * LDT + kk, LDT);
                wmma::load_matrix_sync(al[i], Al + (wm * 32 + i * 16) * LDT + kk, LDT);
            }
#pragma unroll
            for (int j = 0; j < 4; j++) {
                wmma::fragment<wmma::matrix_b, 16, 16, 16, __nv_bfloat16, wmma::col_major> bh, bl;
                wmma::load_matrix_sync(bh, Bh + (wn * 64 + j * 16) * LDT + kk, LDT);
                wmma::load_matrix_sync(bl, Bl + (wn * 64 + j * 16) * LDT + kk, LDT);
#pragma unroll
                for (int i = 0; i < 2; i++) {
                    wmma::mma_sync(acc[i][j], ah[i], bh, acc[i][j]);
                    wmma::mma_sync(acc[i][j], ah[i], bl, acc[i][j]);
                    wmma::mma_sync(acc[i][j], al[i], bh, acc[i][j]);
                }
            }
        }
        __syncthreads();
    }

    float* sC = (float*)smem;
#pragma unroll
    for (int i = 0; i < 2; i++)
#pragma unroll
        for (int j = 0; j < 4; j++)
            wmma::store_matrix_sync(sC + (wm * 32 + i * 16) * 128 + wn * 64 + j * 16,
                                    acc[i][j], 128, wmma::mem_row_major);
    __syncthreads();
#pragma unroll
    for (int i = 0; i < 16; i++) {
        const int f = i * 256 + tid;
        const int r = f >> 5, c4 = f & 31;
        const int gm = rowA0 + r;
        if (gm < M) {
            float4 v = *(float4*)(sC + r * 128 + c4 * 4);
            const int n = n0 + c4 * 4;
            v.x += bias[n + 0];
            v.y += bias[n + 1];
            v.z += bias[n + 2];
            v.w += bias[n + 3];
            *(float4*)(C + (size_t)gm * N + n) = v;
        }
    }
}

// ---------------- inter_cls -------------------------------------------------
__global__ void inter_cls_kernel() {
    __shared__ float sc[SS];
    __shared__ float red[256];
    __shared__ float part[8 * D3];
    const int h = blockIdx.x, b = blockIdx.y;
    const int tid = threadIdx.x, lane = tid & 31, wid = tid >> 5;
    const float* baseq = g_xq + (size_t)b * SS * C3 + h * D3;
    const float* basek = g_xk + (size_t)b * SS * C3 + h * D3;
    const float* basev = g_xv + (size_t)b * SS * C3 + h * D3;

    float qv[6];
#pragma unroll
    for (int i = 0; i < 6; i++) qv[i] = baseq[lane + 32 * i];

    for (int t = wid; t < SS; t += 8) {
        const float* kr = basek + (size_t)t * C3;
        float p = 0.f;
#pragma unroll
        for (int i = 0; i < 6; i++) p += qv[i] * kr[lane + 32 * i];
#pragma unroll
        for (int off = 16; off; off >>= 1) p += __shfl_xor_sync(0xffffffffu, p, off);
        if (lane == 0) sc[t] = p * SCALE_INV;
    }
    __syncthreads();

    float m = -1e30f;
    for (int t = tid; t < SS; t += 256) m = fmaxf(m, sc[t]);
    red[tid] = m; __syncthreads();
    for (int s = 128; s; s >>= 1) { if (tid < s) red[tid] = fmaxf(red[tid], red[tid + s]); __syncthreads(); }
    m = red[0]; __syncthreads();

    float z = 0.f;
    for (int t = tid; t < SS; t += 256) { float e = expf(sc[t] - m); sc[t] = e; z += e; }
    red[tid] = z; __syncthreads();
    for (int s = 128; s; s >>= 1) { if (tid < s) red[tid] += red[tid + s]; __syncthreads(); }
    const float invZ = 1.f / red[0];
    __syncthreads();

    float a[6] = {0.f, 0.f, 0.f, 0.f, 0.f, 0.f};
    for (int t = wid; t < SS; t += 8) {
        const float p = sc[t];
        const float* vr = basev + (size_t)t * C3;
#pragma unroll
        for (int i = 0; i < 6; i++) a[i] += p * vr[lane + 32 * i];
    }
#pragma unroll
    for (int i = 0; i < 6; i++) part[wid * D3 + lane + 32 * i] = a[i];
    __syncthreads();
    if (tid < D3) {
        float s = 0.f;
#pragma unroll
        for (int w = 0; w < 8; w++) s += part[w * D3 + tid];
        g_cls[b * C3 + h * D3 + tid] = s * invZ;
    }
}

// ---------------- temporal attention ----------------------------------------
__global__ void temporal_kernel() {
    __shared__ float qs[8 * 193];
    __shared__ float ks[8 * 193];
    __shared__ float sc[8 * 9];
    __shared__ float cw[8];
    const int p = blockIdx.x, h = blockIdx.y, b = blockIdx.z;
    const int tid = threadIdx.x;
    const size_t bb = (size_t)b * SS * C3;

    for (int e = tid; e < 8 * D3; e += 192) {
        int f = e / D3, j = e - f * D3;
        int tok = f * NP + p + 2;
        qs[f * 193 + j] = g_xq[bb + (size_t)tok * C3 + h * D3 + j];
        ks[f * 193 + j] = g_xv[bb + (size_t)tok * C3 + h * D3 + j];
    }
    __syncthreads();

    if (tid < 64) {
        int f = tid >> 3, g = tid & 7;
        float s = 0.f;
        for (int j = 0; j < D3; j++) s += qs[f * 193 + j] * ks[g * 193 + j];
        sc[f * 9 + g] = s * SCALE_INV;
    }
    __syncthreads();

    if (tid < 8) {
        int f = tid;
        float mx = -1e30f;
        for (int g = 0; g < 8; g++) mx = fmaxf(mx, sc[f * 9 + g]);
        float z = 0.f;
        for (int g = 0; g < 8; g++) { float e = expf(sc[f * 9 + g] - mx); sc[f * 9 + g] = e; z += e; }
        float inv = 1.f / z;
        for (int g = 0; g < 8; g++) sc[f * 9 + g] *= inv;
    }
    __syncthreads();
    if (tid < 8) {
        int g = tid;
        float s = 0.f;
        for (int f = 0; f < 8; f++) s += sc[f * 9 + g];
        cw[g] = s;
    }
    __syncthreads();

    {
        int d = tid;
        float acc = 0.f;
#pragma unroll
        for (int g = 0; g < 8; g++) {
            int tok = g * NP + p + 2;
            acc += cw[g] * g_xk[bb + (size_t)tok * C3 + h * D3 + d];
        }
        g_t1[((size_t)b * PP + p) * C3 + h * D3 + d] = acc;
    }
}

// ---------------- output-stage attention -------------------------------------
__global__ void out_attn_kernel(int xi_base, int nk) {
    extern __shared__ float sm[];
    float* Kb = sm;
    float* qb = sm + nk * 193;
    float* w  = qb + 8 * D3;
    const int xi = xi_base + blockIdx.x;
    const int h = blockIdx.y, b = blockIdx.z;
    const int tid = threadIdx.x, lane = tid & 31, wid = tid >> 5;
    const size_t rbase = (size_t)b * PP * C3 + h * D3;

    for (int e = tid; e < nk * D3; e += 256) {
        int r = e / D3, j = e - r * D3;
        int kp = (nk == 196) ? (r % PP) : (xi + r);
        Kb[r * 193 + j] = g_k2[rbase + (size_t)kp * C3 + j];
    }
    for (int k = tid; k < nk; k += 256) w[k] = 0.f;
    __syncthreads();

    for (int q = wid; q < 196; q += 8) {
        int qp = (xi + q) % PP;
        for (int j = lane; j < D3; j += 32)
            qb[wid * D3 + j] = g_q2[rbase + (size_t)qp * C3 + j];
        __syncwarp();

        float s[7];
        int cnt = 0;
        for (int k = lane; k < nk; k += 32) {
            float d = 0.f;
            const float* kr = Kb + k * 193;
            const float* qr = qb + wid * D3;
            for (int j = 0; j < D3; j++) d += qr[j] * kr[j];
            s[cnt++] = d * SCALE_INV;
        }
        float mx = -1e30f;
        for (int c = 0; c < cnt; c++) mx = fmaxf(mx, s[c]);
#pragma unroll
        for (int off = 16; off; off >>= 1) mx = fmaxf(mx, __shfl_xor_sync(0xffffffffu, mx, off));
        float z = 0.f;
        for (int c = 0; c < cnt; c++) { float e = expf(s[c] - mx); s[c] = e; z += e; }
#pragma unroll
        for (int off = 16; off; off >>= 1) z += __shfl_xor_sync(0xffffffffu, z, off);
        float inv = 1.f / z;
        int c = 0;
        for (int k = lane; k < nk; k += 32, c++) atomicAdd(&w[k], s[c] * inv);
        __syncwarp();
    }
    __syncthreads();

    if (tid < D3) {
        float acc = 0.f;
        for (int k = 0; k < nk; k++) {
            int kp = (nk == 196) ? (k % PP) : (xi + k);
            acc += w[k] * g_v2[rbase + (size_t)kp * C3 + tid];
        }
        g_t2[((size_t)b * FF + xi) * C3 + h * D3 + tid] = acc;
    }
}

// ---------------- final 9 rows per batch -------------------------------------
__global__ void final_rows_kernel(const float* __restrict__ Wf, const float* __restrict__ bf) {
    extern __shared__ float As[];
    const int cb = blockIdx.x, b = blockIdx.y;
    const int tid = threadIdx.x;
    for (int e = tid; e < 9 * C3; e += 192) {
        int r = e / C3, k = e - r * C3;
        As[e] = (r == 0) ? g_cls[b * C3 + k] : g_t2[((size_t)b * FF + (r - 1)) * C3 + k];
    }
    __syncthreads();
    const int c = cb * 192 + tid;
    float acc[9];
#pragma unroll
    for (int r = 0; r < 9; r++) acc[r] = 0.f;
    for (int k = 0; k < C3; k++) {
        float wv = Wf[(size_t)k * DIMM + c];
#pragma unroll
        for (int r = 0; r < 9; r++) acc[r] += As[r * C3 + k] * wv;
    }
    float bv = bf[c];
#pragma unroll
    for (int r = 0; r < 9; r++)
        g_rows[((size_t)b * 9 + r) * DIMM + c] = acc[r] + bv;
}

// ---------------- broadcast -> output -----------------------------------------
__global__ void bcast_kernel(float* __restrict__ out) {
    size_t i4 = (size_t)blockIdx.x * blockDim.x + threadIdx.x;
    const size_t total4 = (size_t)BB * SS * DIMM / 4;
    if (i4 >= total4) return;
    size_t idx = i4 * 4;
    int c = idx % DIMM;
    size_t rs = idx / DIMM;
    int s = rs % SS;
    int b = rs / SS;
    int r = (s == 0) ? 0 : 1 + ((s - 1) & 7);
    ((float4*)out)[i4] = *(const float4*)(g_rows + ((size_t)b * 9 + r) * DIMM + c);
}

// ---------------- launch ------------------------------------------------------
extern "C" void kernel_launch(void* const* d_in, const int* in_sizes, int n_in,
                              void* d_out, int out_size) {
    const float* x  = (const float*)d_in[0];
    const float* Wq = (const float*)d_in[1];
    const float* bq = (const float*)d_in[2];
    const float* Wk = (const float*)d_in[3];
    const float* bk = (const float*)d_in[4];
    const float* Wv = (const float*)d_in[5];
    const float* bv = (const float*)d_in[6];
    const float* Wt = (const float*)d_in[7];
    const float* bt = (const float*)d_in[8];
    const float* Wf = (const float*)d_in[9];
    const float* bf = (const float*)d_in[10];
    float* out = (float*)d_out;

    float *p_xq, *p_xk, *p_xv, *p_t1, *p_ti, *p_q2, *p_k2, *p_v2;
    cudaGetSymbolAddress((void**)&p_xq, g_xq);
    cudaGetSymbolAddress((void**)&p_xk, g_xk);
    cudaGetSymbolAddress((void**)&p_xv, g_xv);
    cudaGetSymbolAddress((void**)&p_t1, g_t1);
    cudaGetSymbolAddress((void**)&p_ti, g_ti);
    cudaGetSymbolAddress((void**)&p_q2, g_q2);
    cudaGetSymbolAddress((void**)&p_k2, g_k2);
    cudaGetSymbolAddress((void**)&p_v2, g_v2);
    __nv_bfloat16 *p_xhi, *p_xlo, *p_t1hi, *p_t1lo, *p_tihi, *p_tilo;
    __nv_bfloat16 *p_Wqhi, *p_Wqlo, *p_Wkhi, *p_Wklo, *p_Wvhi, *p_Wvlo, *p_Wthi, *p_Wtlo;
    cudaGetSymbolAddress((void**)&p_xhi, g_xhi);
    cudaGetSymbolAddress((void**)&p_xlo, g_xlo);
    cudaGetSymbolAddress((void**)&p_t1hi, g_t1hi);
    cudaGetSymbolAddress((void**)&p_t1lo, g_t1lo);
    cudaGetSymbolAddress((void**)&p_tihi, g_tihi);
    cudaGetSymbolAddress((void**)&p_tilo, g_tilo);
    cudaGetSymbolAddress((void**)&p_Wqhi, g_WqThi);
    cudaGetSymbolAddress((void**)&p_Wqlo, g_WqTlo);
    cudaGetSymbolAddress((void**)&p_Wkhi, g_WkThi);
    cudaGetSymbolAddress((void**)&p_Wklo, g_WkTlo);
    cudaGetSymbolAddress((void**)&p_Wvhi, g_WvThi);
    cudaGetSymbolAddress((void**)&p_Wvlo, g_WvTlo);
    cudaGetSymbolAddress((void**)&p_Wthi, g_WtThi);
    cudaGetSymbolAddress((void**)&p_Wtlo, g_WtTlo);

    const size_t BIG_SMEM = 2 * (size_t)BSTAGE;         // 122880
    const size_t GEMM_SMEM = (size_t)NSTAGE * STAGE_B;  // 81920
    cudaFuncSetAttribute(gemm_big, cudaFuncAttributeMaxDynamicSharedMemorySize, (int)BIG_SMEM);
    cudaFuncSetAttribute(gemm_bs, cudaFuncAttributeMaxDynamicSharedMemorySize, (int)GEMM_SMEM);
    cudaFuncSetAttribute(out_attn_kernel, cudaFuncAttributeMaxDynamicSharedMemorySize, 160000);
    cudaFuncSetAttribute(final_rows_kernel, cudaFuncAttributeMaxDynamicSharedMemorySize, 9 * C3 * 4);

    transpose_split<<<dim3(C3 / 32, DIMM / 32), 256>>>(Wq, p_Wqhi, p_Wqlo, DIMM, C3);
    transpose_split<<<dim3(C3 / 32, DIMM / 32), 256>>>(Wk, p_Wkhi, p_Wklo, DIMM, C3);
    transpose_split<<<dim3(C3 / 32, DIMM / 32), 256>>>(Wv, p_Wvhi, p_Wvlo, DIMM, C3);
    transpose_split<<<dim3(DIMM / 32, C3 / 32), 256>>>(Wt, p_Wthi, p_Wtlo, C3, DIMM);
    {
        int n4 = BB * SS * DIMM / 4;
        split_f32<<<(n4 + 255) / 256, 256>>>(x, p_xhi, p_xlo, n4);
    }

    const int M1 = BB * SS;   // 12552
    {
        dim3 grid(C3 / 256, M1PAD / 128);
        gemm_big<<<grid, 256, BIG_SMEM>>>(p_xhi, p_xlo, p_Wqhi, p_Wqlo, bq, p_xq, M1, C3, DIMM);
        gemm_big<<<grid, 256, BIG_SMEM>>>(p_xhi, p_xlo, p_Wkhi, p_Wklo, bk, p_xk, M1, C3, DIMM);
        gemm_big<<<grid, 256, BIG_SMEM>>>(p_xhi, p_xlo, p_Wvhi, p_Wvlo, bv, p_xv, M1, C3, DIMM);
    }
    inter_cls_kernel<<<dim3(HH, BB), 256>>>();
    temporal_kernel<<<dim3(PP, HH, BB), 192>>>();

    const int M2 = BB * PP;   // 1560
    {
        int n4 = M2 * C3 / 4;
        split_f32<<<(n4 + 255) / 256, 256>>>(p_t1, p_t1hi, p_t1lo, n4);
        dim3 grid(DIMM / 128, M2PAD / 128);
        gemm_bs<<<grid, 256, GEMM_SMEM>>>(p_t1hi, p_t1lo, p_Wthi, p_Wtlo, bt, p_ti, M2, DIMM, C3);
    }
    {
        int n4 = M2 * DIMM / 4;
        split_f32<<<(n4 + 255) / 256, 256>>>(p_ti, p_tihi, p_tilo, n4);
        dim3 grid(C3 / 256, M2PAD / 128);
        gemm_big<<<grid, 256, BIG_SMEM>>>(p_tihi, p_tilo, p_Wqhi, p_Wqlo, bq, p_q2, M2, C3, DIMM);
        gemm_big<<<grid, 256, BIG_SMEM>>>(p_tihi, p_tilo, p_Wvhi, p_Wvlo, bv, p_k2, M2, C3, DIMM);
        gemm_big<<<grid, 256, BIG_SMEM>>>(p_tihi, p_tilo, p_Wkhi, p_Wklo, bk, p_v2, M2, C3, DIMM);
    }
    {
        size_t smA = (size_t)(196 * 193 + 8 * D3 + 196) * 4;
        out_attn_kernel<<<dim3(1, HH, BB), 256, smA>>>(0, 196);
        size_t smB = (size_t)(8 * 193 + 8 * D3 + 8) * 4;
        out_attn_kernel<<<dim3(7, HH, BB), 256, smB>>>(1, 8);
    }
    final_rows_kernel<<<dim3(4, BB), 192, (size_t)9 * C3 * 4>>>(Wf, bf);
    {
        const size_t total4 = (size_t)BB * SS * DIMM / 4;
        bcast_kernel<<<(unsigned)((total4 + 255) / 256), 256>>>(out);
    }
}